// round 5
// baseline (speedup 1.0000x reference)
#include <cuda_runtime.h>
#include <cuda_bf16.h>

// ---------------------------------------------------------------------------
// DownSample: FPS(64->32 strokes) + gathers + conv(1x3,s=2,p=1) 128->256 +
// BatchNorm(batch stats, fused partial sums) + tanh-GELU.
//
// Output layout in d_out (float32):
//   [0        , 524288)    sparse_out      [64,256,32]
//   [524288   , 17301504)  dense_out       [64,256,1024]
//   [17301504 , 17367040)  stk_coor_sampled[64,32,32]
// ---------------------------------------------------------------------------

#define N_STK      64
#define N_HALF     32
#define N_PNT      64
#define COOR_EMB   32
#define BS         64
#define C_IN       128
#define C_OUT      256
#define SP_EMB     256
#define NBLK       (BS * N_HALF)      // 2048 conv blocks

__device__ __align__(16) int    g_fps_idx[BS * N_HALF];
__device__ __align__(16) unsigned long long g_wp[C_IN * C_OUT * 4]; // dup pairs [i][o][k0,k1,k2,pad]
__device__ __align__(16) float  g_y[(size_t)BS * C_OUT * 1024];     // conv out (64 MB)
__device__ __align__(16) float2 g_ps[NBLK * C_OUT];                 // per-block (sum, sumsq)
__device__ __align__(16) float  g_scale[C_OUT];
__device__ __align__(16) float  g_shift[C_OUT];

// ---------------- f32x2 packed helpers (sm_103a) ----------------
__device__ __forceinline__ void unpack2(unsigned long long v, float& x, float& y) {
    asm("mov.b64 {%0, %1}, %2;" : "=f"(x), "=f"(y) : "l"(v));
}
__device__ __forceinline__ unsigned long long fma2(unsigned long long a,
                                                   unsigned long long b,
                                                   unsigned long long c) {
    unsigned long long d;
    asm("fma.rn.f32x2 %0, %1, %2, %3;" : "=l"(d) : "l"(a), "l"(b), "l"(c));
    return d;
}

// ---------------- K1: farthest point sampling -------------------
__global__ void fps_kernel(const float* __restrict__ coor, float* __restrict__ coor_out) {
    int b = blockIdx.x;
    int n = threadIdx.x;

    float p[COOR_EMB];
    const float4* src = (const float4*)(coor + ((size_t)b * N_STK + n) * COOR_EMB);
#pragma unroll
    for (int q = 0; q < COOR_EMB / 4; q++) {
        float4 v = src[q];
        p[4 * q + 0] = v.x; p[4 * q + 1] = v.y; p[4 * q + 2] = v.z; p[4 * q + 3] = v.w;
    }

    __shared__ __align__(16) float cen[COOR_EMB];
    __shared__ float sd[N_STK];
    __shared__ int   si[N_STK];

    float dist = 1e10f;
    int farthest = 0;

    for (int it = 0; it < N_HALF; it++) {
        if (n == 0) g_fps_idx[b * N_HALF + it] = farthest;
        if (n == farthest) {
            float* co = coor_out + ((size_t)b * N_HALF + it) * COOR_EMB;
#pragma unroll
            for (int c = 0; c < COOR_EMB; c++) { cen[c] = p[c]; co[c] = p[c]; }
        }
        __syncthreads();

        float d = 0.f;
#pragma unroll
        for (int c = 0; c < COOR_EMB; c++) {
            float df = p[c] - cen[c];
            d = fmaf(df, df, d);
        }
        dist = fminf(dist, d);

        sd[n] = dist; si[n] = n;
        __syncthreads();
#pragma unroll
        for (int st = 32; st > 0; st >>= 1) {
            if (n < st) {
                float dv = sd[n + st]; int iv = si[n + st];
                if (dv > sd[n] || (dv == sd[n] && iv < si[n])) { sd[n] = dv; si[n] = iv; }
            }
            __syncthreads();
        }
        farthest = si[0];
        __syncthreads();
    }
}

// ---------------- K2: fused sparse gather + weight dup-transpose ----
// blocks [0, 2048): gather sparse_out; blocks [2048, 2560): build g_wp.
__global__ void prep_kernel(const float* __restrict__ sp, const float* __restrict__ w,
                            float* __restrict__ sparse_out) {
    int blk = blockIdx.x;
    int tid = threadIdx.x;
    if (blk < 2048) {
        int gid = blk * 256 + tid;               // BS*SP_EMB*N_HALF = 524288
        int s = gid & 31;
        int e = (gid >> 5) & 255;
        int b = gid >> 13;
        int sid = g_fps_idx[b * N_HALF + s];
        sparse_out[gid] = sp[((size_t)b * SP_EMB + e) * N_STK + sid];
    } else {
        int idx = (blk - 2048) * 256 + tid;      // C_IN*C_OUT*4 = 131072
        int k = idx & 3;
        int o = (idx >> 2) & 255;
        int i = idx >> 10;
        float wv = (k < 3) ? w[o * (C_IN * 3) + i * 3 + k] : 0.f;
        unsigned int u = __float_as_uint(wv);
        g_wp[idx] = (unsigned long long)u | ((unsigned long long)u << 32);
    }
}

// ---------------- K3: gathered strided conv (deferred shift) -----
// block = (stroke s, batch b); 128 threads; thread t owns channels t, t+128.
// y[p'] = w0*v[p'-1] + w1*u[p'] + w2*v[p'] summed over i (u=even, v=odd taps)
// Z_j += w1*U_j + w2*V_j ; A_j += w0*V_j  (all aligned)
// epilogue: y[2j] = Z_j.lo + A_{j-1}.hi ;  y[2j+1] = Z_j.hi + A_j.lo
#define ROWP 36
#define CSTEP(j, Uv, Vv)                  \
    Z0[j] = fma2(Uv, WA1, Z0[j]);         \
    Z0[j] = fma2(Vv, WA2, Z0[j]);         \
    A0[j] = fma2(Vv, WA0, A0[j]);         \
    Z1[j] = fma2(Uv, WB1, Z1[j]);         \
    Z1[j] = fma2(Vv, WB2, Z1[j]);         \
    A1[j] = fma2(Vv, WB0, A1[j]);

__global__ __launch_bounds__(128, 2) void conv_kernel(const float* __restrict__ dense,
                                                      const float* __restrict__ bias) {
    __shared__ __align__(16) float sbuf[2 * C_IN * ROWP];   // 36.9 KB
    float* su = sbuf;
    float* sv = sbuf + C_IN * ROWP;

    int s = blockIdx.x;
    int b = blockIdx.y;
    int t = threadIdx.x;

    int sid = g_fps_idx[b * N_HALF + s];
    const float* src = dense + (size_t)b * C_IN * (N_STK * N_PNT) + sid * N_PNT;

    // fill: thread t loads channel row t (64 floats), deinterleaves even/odd
    {
        const float4* r = (const float4*)(src + (size_t)t * (N_STK * N_PNT));
        float* pu = su + t * ROWP;
        float* pv = sv + t * ROWP;
#pragma unroll
        for (int q = 0; q < 16; q++) {
            float4 x = r[q];
            pu[2 * q]     = x.x;   // u[2q]   = d[4q]
            pu[2 * q + 1] = x.z;   // u[2q+1] = d[4q+2]
            pv[2 * q]     = x.y;   // v[2q]   = d[4q+1]
            pv[2 * q + 1] = x.w;   // v[2q+1] = d[4q+3]
        }
    }
    __syncthreads();

    unsigned long long A0[16], Z0[16], A1[16], Z1[16];
#pragma unroll
    for (int j = 0; j < 16; j++) { A0[j] = 0ULL; Z0[j] = 0ULL; A1[j] = 0ULL; Z1[j] = 0ULL; }

    for (int i = 0; i < C_IN; i++) {
        size_t wia = ((size_t)(i << 8) + t) * 4;
        size_t wib = ((size_t)(i << 8) + t + 128) * 4;
        ulonglong2 wa01 = *(const ulonglong2*)(g_wp + wia);
        ulonglong2 wb01 = *(const ulonglong2*)(g_wp + wib);
        unsigned long long WA0 = wa01.x, WA1 = wa01.y, WA2 = g_wp[wia + 2];
        unsigned long long WB0 = wb01.x, WB1 = wb01.y, WB2 = g_wp[wib + 2];
        const float* ru = su + i * ROWP;
        const float* rv = sv + i * ROWP;
#pragma unroll
        for (int c = 0; c < 4; c++) {
            ulonglong2 Ua = *(const ulonglong2*)(ru + 8 * c);
            ulonglong2 Va = *(const ulonglong2*)(rv + 8 * c);
            ulonglong2 Ub = *(const ulonglong2*)(ru + 8 * c + 4);
            ulonglong2 Vb = *(const ulonglong2*)(rv + 8 * c + 4);
            CSTEP(4 * c + 0, Ua.x, Va.x)
            CSTEP(4 * c + 1, Ua.y, Va.y)
            CSTEP(4 * c + 2, Ub.x, Vb.x)
            CSTEP(4 * c + 3, Ub.y, Vb.y)
        }
    }
    __syncthreads();

    // epilogue: shift-combine + bias; accumulate per-channel BN partials
    float bv0 = bias[t], bv1 = bias[t + 128];
    float* sy = sbuf;   // 256*33 = 8448 floats <= 9216 available
    float ph0 = 0.f, ph1 = 0.f;
    float s0 = 0.f, q0 = 0.f, s1 = 0.f, q1 = 0.f;
#pragma unroll
    for (int j = 0; j < 16; j++) {
        float zl, zh, al, ah;
        unpack2(Z0[j], zl, zh); unpack2(A0[j], al, ah);
        float y0 = zl + ph0 + bv0;
        float y1 = zh + al + bv0;
        ph0 = ah;
        sy[t * 33 + 2 * j]     = y0;
        sy[t * 33 + 2 * j + 1] = y1;
        s0 += y0 + y1;
        q0 = fmaf(y0, y0, q0); q0 = fmaf(y1, y1, q0);

        unpack2(Z1[j], zl, zh); unpack2(A1[j], al, ah);
        float w0 = zl + ph1 + bv1;
        float w1 = zh + al + bv1;
        ph1 = ah;
        sy[(t + 128) * 33 + 2 * j]     = w0;
        sy[(t + 128) * 33 + 2 * j + 1] = w1;
        s1 += w0 + w1;
        q1 = fmaf(w0, w0, q1); q1 = fmaf(w1, w1, q1);
    }
    int k = b * N_HALF + s;
    g_ps[(size_t)k * C_OUT + t]       = make_float2(s0, q0);
    g_ps[(size_t)k * C_OUT + t + 128] = make_float2(s1, q1);
    __syncthreads();

    float* dst = g_y + (size_t)b * C_OUT * 1024 + s * 32;
    for (int e = t; e < C_OUT * 32; e += 128) {
        int o2 = e >> 5, p = e & 31;
        dst[(size_t)o2 * 1024 + p] = sy[o2 * 33 + p];
    }
}

// ---------------- K4: BN finish (reduce partials) ---------------
__global__ void bn_finish(const float* __restrict__ gamma, const float* __restrict__ beta) {
    int o = blockIdx.x;
    int t = threadIdx.x;  // 256
    float S = 0.f, Q = 0.f;
    for (int k = t; k < NBLK; k += 256) {
        float2 p = g_ps[(size_t)k * C_OUT + o];
        S += p.x; Q += p.y;
    }
    __shared__ float rs[256], rq[256];
    rs[t] = S; rq[t] = Q;
    __syncthreads();
    for (int st = 128; st > 0; st >>= 1) {
        if (t < st) { rs[t] += rs[t + st]; rq[t] += rq[t + st]; }
        __syncthreads();
    }
    if (t == 0) {
        const float inv_n = 1.f / 65536.f;
        float mean = rs[0] * inv_n;
        float var  = rq[0] * inv_n - mean * mean;
        float r    = rsqrtf(var + 1e-5f);
        float sc   = gamma[o] * r;
        g_scale[o] = sc;
        g_shift[o] = beta[o] - mean * sc;
    }
}

// ---------------- K5: normalize + GELU --------------------------
__device__ __forceinline__ float gelu_f(float x) {
    float z = 0.7978845608028654f * fmaf(0.044715f * x, x * x, x);
    float e = __expf(2.f * z);
    float th = 1.f - __fdividef(2.f, e + 1.f);
    return 0.5f * x * (1.f + th);
}

__global__ void bn_gelu(float* __restrict__ out) {
    int i = blockIdx.x * blockDim.x + threadIdx.x;
    if (i < (BS * C_OUT * 1024) / 4) {
        float4 v = ((const float4*)g_y)[i];
        int o = (i >> 8) & 255;
        float sc = g_scale[o], sh = g_shift[o];
        v.x = gelu_f(fmaf(v.x, sc, sh));
        v.y = gelu_f(fmaf(v.y, sc, sh));
        v.z = gelu_f(fmaf(v.z, sc, sh));
        v.w = gelu_f(fmaf(v.w, sc, sh));
        ((float4*)out)[i] = v;
    }
}

// ---------------- launch ----------------------------------------
extern "C" void kernel_launch(void* const* d_in, const int* in_sizes, int n_in,
                              void* d_out, int out_size) {
    const float* sparse_fea = (const float*)d_in[0];   // [64,256,64]
    const float* dense_fea  = (const float*)d_in[1];   // [64,128,4096]
    const float* stk_coor   = (const float*)d_in[2];   // [64,64,32]
    const float* conv_w     = (const float*)d_in[3];   // [256,128,1,3]
    const float* conv_b     = (const float*)d_in[4];   // [256]
    const float* bn_gamma   = (const float*)d_in[5];   // [256]
    const float* bn_beta    = (const float*)d_in[6];   // [256]

    float* out = (float*)d_out;
    float* sparse_out = out;                            // 524288
    float* dense_out  = out + 524288;                   // 16777216
    float* coor_out   = out + 524288 + 16777216;        // 65536

    fps_kernel<<<BS, N_STK>>>(stk_coor, coor_out);
    prep_kernel<<<2048 + 512, 256>>>(sparse_fea, conv_w, sparse_out);
    conv_kernel<<<dim3(N_HALF, BS), 128>>>(dense_fea, conv_b);
    bn_finish<<<C_OUT, 256>>>(bn_gamma, bn_beta);
    bn_gelu<<<(BS * C_OUT * 1024 / 4 + 255) / 256, 256>>>(dense_out);
}